// round 8
// baseline (speedup 1.0000x reference)
#include <cuda_runtime.h>
#include <math.h>

// ---------------------------------------------------------------------------
// CombinedSOTALoss, pred/target [B,1,1024,1024] fp32 (B=16), scalar output.
//  k_main      : sigmoid + dice/focal/connectivity sums + binary maps (packed)
//  5x k_erode2 : TWO skeleton iterations per launch (shared-mem fused),
//                uint8 {0,1,2}, 4 px/thread packed, exact integer sums,
//                sequential convergence state machine in last-ticket block
//  k_skelfinal : packed sobel on binaries + clip + skeleton-dice sums;
//                last block computes the final scalar and resets all state.
// ---------------------------------------------------------------------------

#define HH 1024
#define WW 1024
#define MAXB 16
#define NPIX (MAXB * HH * WW)
#define TX 32
#define TY 16
#define NT (TX * TY)
#define NITER 10
#define NF (NITER / 2)
#define EW 128            // tile width in pixels
#define WPR 34            // 4-px words per tile row incl 1-word halo each side
#define WPAD 36           // padded shared row stride (words)
#define WF 136            // floats per shared row (EW + 8)
#define M01 0x01010101u

__device__ unsigned char g_bin[2][NPIX];   // [0]=pred binary, [1]=target binary
__device__ unsigned char g_skA[2][NPIX];   // even-iteration results
__device__ unsigned char g_skB[2][NPIX];   // odd-iteration results
__device__ unsigned long long g_itersum[NITER][2];
__device__ unsigned int g_count[NITER][2];
__device__ unsigned int g_cnt_sf;
__device__ int       g_done[2];
__device__ long long g_prev[2] = {-1LL, -1LL};
__device__ int       g_parity[2];          // 0 -> final skel in g_skA else g_skB
__device__ double    g_acc[8];
// 0 dice_inter, 1 sum_p, 2 sum_t, 3 focal, 4 conn, 5 sk_inter, 6 sk_p, 7 sk_t

// ---------------------------------------------------------------------------
__device__ __forceinline__ float block_reduce(float v, float* wb) {
    const int tid  = threadIdx.y * TX + threadIdx.x;
    const int lane = tid & 31;
    const int wid  = tid >> 5;
#pragma unroll
    for (int o = 16; o; o >>= 1) v += __shfl_down_sync(0xffffffffu, v, o);
    __syncthreads();                 // protects wb across successive calls
    if (lane == 0) wb[wid] = v;
    __syncthreads();
    float r = 0.f;
    if (tid < (NT / 32)) r = wb[tid];
    if (wid == 0) {
#pragma unroll
        for (int o = (NT / 64); o; o >>= 1)
            r += __shfl_down_sync(0xffffffffu, r, o);
    }
    return r;   // valid on tid 0
}

__device__ __forceinline__ float sigm(float x) {
    return 1.f / (1.f + __expf(-x));
}

// per-byte erosion step: given 3x3 byte-sum s9 and current value sk:
// er = (byte >= 9); nv = er=0 ? 0 : (sk==1 ? 2 : 1)
__device__ __forceinline__ unsigned int erode_bytes(unsigned int s9,
                                                    unsigned int sk) {
    const unsigned int er  = ((s9 + 0x77777777u) >> 7) & M01;
    const unsigned int eq1 = (sk & M01) & ~((sk >> 1) & M01);
    return er + (er & eq1);
}

// ---------------------------------------------------------------------------
// Main pass: tile 128x16, 4 px/thread. sigmoid, dice/focal sums,
// conn = conv3x3(p - t)/9 (separable, linearity of conv), packed binary maps.
// ---------------------------------------------------------------------------
__global__ void __launch_bounds__(NT)
k_main(const float* __restrict__ pred, const float* __restrict__ tgt, int B) {
    __shared__ float sp[TY + 2][WF];
    __shared__ float sd[TY + 2][WF];
    __shared__ unsigned char st8[TY + 2][WF];
    __shared__ float vsm[TY][WF];
    __shared__ float wb[NT / 32];

    const int ox = blockIdx.x * EW, oy = blockIdx.y * TY;
    const int tid = threadIdx.y * TX + threadIdx.x;
    float a0 = 0.f, a1 = 0.f, a3 = 0.f, a4 = 0.f;
    int   acc_t = 0;

    for (int b = 0; b < B; b++) {
        const size_t base = (size_t)b * HH * WW;
        __syncthreads();
        for (int i = tid; i < (TY + 2) * WPR; i += NT) {
            const int ly = i / WPR, lw = i - ly * WPR;
            const int gy = oy - 1 + ly, gx0 = ox - 4 + 4 * lw;
            float4 s4 = make_float4(0.f, 0.f, 0.f, 0.f);
            float4 d4 = s4;
            unsigned int tw = 0u;
            if ((unsigned)gy < HH && (unsigned)gx0 <= (WW - 4)) {
                const size_t idx = base + (size_t)gy * WW + gx0;
                const float4 pv = *(const float4*)(pred + idx);
                const float4 tv = *(const float4*)(tgt + idx);
                s4.x = sigm(pv.x); s4.y = sigm(pv.y);
                s4.z = sigm(pv.z); s4.w = sigm(pv.w);
                d4.x = s4.x - tv.x; d4.y = s4.y - tv.y;
                d4.z = s4.z - tv.z; d4.w = s4.w - tv.w;
                tw = (unsigned int)tv.x | ((unsigned int)tv.y << 8)
                   | ((unsigned int)tv.z << 16) | ((unsigned int)tv.w << 24);
            }
            *(float4*)&sp[ly][4 * lw] = s4;
            *(float4*)&sd[ly][4 * lw] = d4;
            *(unsigned int*)&st8[ly][4 * lw] = tw;
        }
        __syncthreads();
        for (int i = tid; i < TY * WPR; i += NT) {
            const int vy = i / WPR, vw = 4 * (i - vy * WPR);
            const float4 r0 = *(const float4*)&sd[vy][vw];
            const float4 r1 = *(const float4*)&sd[vy + 1][vw];
            const float4 r2 = *(const float4*)&sd[vy + 2][vw];
            float4 v;
            v.x = r0.x + r1.x + r2.x; v.y = r0.y + r1.y + r2.y;
            v.z = r0.z + r1.z + r2.z; v.w = r0.w + r1.w + r2.w;
            *(float4*)&vsm[vy][vw] = v;
        }
        __syncthreads();

        const int ty = threadIdx.y;
        const int x0 = 4 * threadIdx.x;
        unsigned int pb = 0u;
        const unsigned int tw = *(const unsigned int*)&st8[ty + 1][4 + x0];
#pragma unroll
        for (int k = 0; k < 4; k++) {
            const int c = 4 + x0 + k;
            const float p = sp[ty + 1][c];
            const int   ti = (tw >> (8 * k)) & 0xFF;

            const float cv = vsm[ty][c - 1] + vsm[ty][c] + vsm[ty][c + 1];
            const float dv = cv * (1.f / 9.f);
            if (ti) a4 += dv * dv;

            const float pc = fminf(fmaxf(p, 1e-6f), 1.f - 1e-6f);
            float bce, pt, at;
            if (ti) { bce = -__logf(pc);       pt = pc;       at = 0.25f; }
            else    { bce = -__logf(1.f - pc); pt = 1.f - pc; at = 0.75f; }
            const float om = 1.f - pt;
            a3 += at * om * om * bce;
            a1 += p;
            if (ti) a0 += p;
            if (p > 0.5f) pb |= 1u << (8 * k);
        }
        acc_t = __dp4a((int)tw, (int)M01, acc_t);

        const size_t o = base + (size_t)(oy + ty) * WW + (ox + x0);
        *(unsigned int*)(g_bin[0] + o) = pb;
        *(unsigned int*)(g_bin[1] + o) = tw;
    }

    float r;
    r = block_reduce(a0, wb);            if (tid == 0) atomicAdd(&g_acc[0], (double)r);
    r = block_reduce(a1, wb);            if (tid == 0) atomicAdd(&g_acc[1], (double)r);
    r = block_reduce((float)acc_t, wb);  if (tid == 0) atomicAdd(&g_acc[2], (double)r);
    r = block_reduce(a3, wb);            if (tid == 0) atomicAdd(&g_acc[3], (double)r);
    r = block_reduce(a4, wb);            if (tid == 0) atomicAdd(&g_acc[4], (double)r);
}

// ---------------------------------------------------------------------------
// TWO fused skeleton iterations (2f -> skA, 2f+1 -> skB), both skeletons via
// blockIdx.z. Tile 128x16, halo: 1 word (4px) each side, 2 rows top/bottom.
// All byte sums <= 18 -> packed adds never carry across byte lanes.
// Edge words use clamped neighbors; the polluted bytes (word0 byte0 /
// word33 byte3 of e0, and their vs1 images) never feed a stored result.
// ---------------------------------------------------------------------------
__global__ void __launch_bounds__(NT)
k_erode2(int f, int B) {
    const int s = blockIdx.z;
    if (g_done[s]) return;

    const unsigned char* __restrict__ src = (f == 0) ? g_bin[s] : g_skB[s];
    unsigned char* __restrict__ dstA = g_skA[s];
    unsigned char* __restrict__ dstB = g_skB[s];

    __shared__ unsigned int raw[TY + 4][WPAD];   // src, rows gy = oy-2+ly
    __shared__ unsigned int vs0[TY + 2][WPAD];   // col sums, center gy = oy-1+r
    __shared__ unsigned int e0s[TY + 2][WPAD];   // iter-A result, gy = oy-1+r
    __shared__ unsigned int vs1[TY][WPAD];       // col sums of e0, gy = oy+t
    __shared__ float wb[NT / 32];

    const int ox = blockIdx.x * EW, oy = blockIdx.y * TY;
    const int tid = threadIdx.y * TX + threadIdx.x;
    int acc0 = 0, acc1 = 0;

    for (int b = 0; b < B; b++) {
        const size_t base = (size_t)b * HH * WW;
        __syncthreads();
        for (int i = tid; i < (TY + 4) * WPR; i += NT) {
            const int ly = i / WPR, lw = i - ly * WPR;
            const int gy = oy - 2 + ly, gx0 = ox - 4 + 4 * lw;
            unsigned int v = 0;
            if ((unsigned)gy < HH && (unsigned)gx0 <= (WW - 4))
                v = *(const unsigned int*)(src + base + (size_t)gy * WW + gx0);
            raw[ly][lw] = v;
        }
        __syncthreads();
        for (int i = tid; i < (TY + 2) * WPR; i += NT) {
            const int r = i / WPR, w = i - r * WPR;
            vs0[r][w] = raw[r][w] + raw[r + 1][w] + raw[r + 2][w];
        }
        __syncthreads();
        for (int i = tid; i < (TY + 2) * WPR; i += NT) {
            const int r = i / WPR, w = i - r * WPR;
            const unsigned int vc = vs0[r][w];
            const unsigned int vl = (w > 0)       ? vs0[r][w - 1] : 0u;
            const unsigned int vr = (w < WPR - 1) ? vs0[r][w + 1] : 0u;
            const unsigned int s9 = __byte_perm(vc, vl, 0x2107) + vc
                                  + __byte_perm(vc, vr, 0x4321);
            e0s[r][w] = erode_bytes(s9, raw[r + 1][w]);
        }
        __syncthreads();
        for (int i = tid; i < TY * WPR; i += NT) {
            const int t = i / WPR, w = i - t * WPR;
            vs1[t][w] = e0s[t][w] + e0s[t + 1][w] + e0s[t + 2][w];
        }
        __syncthreads();

        const int w = threadIdx.x + 1, ty = threadIdx.y;
        const unsigned int vc = vs1[ty][w];
        const unsigned int vl = vs1[ty][w - 1];
        const unsigned int vr = vs1[ty][w + 1];
        const unsigned int s9 = __byte_perm(vc, vl, 0x2107) + vc
                              + __byte_perm(vc, vr, 0x4321);
        const unsigned int nv0 = e0s[ty + 1][w];        // iter-A, center
        const unsigned int nv1 = erode_bytes(s9, nv0);  // iter-B

        const size_t o = base + (size_t)(oy + ty) * WW + (ox + 4 * threadIdx.x);
        *(unsigned int*)(dstA + o) = nv0;
        *(unsigned int*)(dstB + o) = nv1;
        acc0 = __dp4a((int)nv0, (int)M01, acc0);
        acc1 = __dp4a((int)nv1, (int)M01, acc1);
    }

    float r0 = block_reduce((float)acc0, wb);   // <= 2^17, exact in fp32
    if (tid == 0 && r0 != 0.f)
        atomicAdd(&g_itersum[2 * f][s], (unsigned long long)(long long)r0);
    float r1 = block_reduce((float)acc1, wb);
    if (tid == 0 && r1 != 0.f)
        atomicAdd(&g_itersum[2 * f + 1][s], (unsigned long long)(long long)r1);

    if (tid == 0) {
        __threadfence();
        const unsigned int nb = gridDim.x * gridDim.y;
        const unsigned int tkt = atomicAdd(&g_count[f][s], 1u);
        if (tkt == nb - 1) {   // last block: sequential 2-step convergence
            const long long s0 =
                (long long)atomicAdd(&g_itersum[2 * f][s], 0ull);
            const long long s1 =
                (long long)atomicAdd(&g_itersum[2 * f + 1][s], 0ull);
            int d = 0;
            g_parity[s] = 0;                       // iter 2f updated skel (skA)
            if (g_prev[s] >= 0 && s0 == g_prev[s]) d = 1;
            g_prev[s] = s0;
            if (!d) {
                g_parity[s] = 1;                   // iter 2f+1 updated (skB)
                if (s1 == g_prev[s]) d = 1;
                g_prev[s] = s1;
            }
            if (d) g_done[s] = 1;
            __threadfence();
        }
    }
}

// ---------------------------------------------------------------------------
// Final: packed sobel on binaries (sign irrelevant: only squares used),
// s = min(skel + 0.5*sqrt(gx^2+gy^2+1e-8), 1); skeleton-dice sums.
// Last block combines everything -> out[0] and resets device state.
// ---------------------------------------------------------------------------
__global__ void __launch_bounds__(NT)
k_skelfinal(int B, float* __restrict__ out) {
    __shared__ unsigned int rp[TY + 2][WPAD], rt[TY + 2][WPAD];
    __shared__ unsigned int hp[TY + 2][WPAD], ht[TY + 2][WPAD];
    __shared__ unsigned int vp[TY][WPAD],     vt[TY][WPAD];
    __shared__ float lut[33];
    __shared__ float wb[NT / 32];
    __shared__ int   slast;

    const unsigned char* __restrict__ skp = g_parity[0] ? g_skB[0] : g_skA[0];
    const unsigned char* __restrict__ skt = g_parity[1] ? g_skB[1] : g_skA[1];

    const int ox = blockIdx.x * EW, oy = blockIdx.y * TY;
    const int tid = threadIdx.y * TX + threadIdx.x;
    if (tid < 33) lut[tid] = sqrtf((float)tid + 1e-8f);
    float a5 = 0.f, a6 = 0.f, a7 = 0.f;

    for (int b = 0; b < B; b++) {
        const size_t base = (size_t)b * HH * WW;
        __syncthreads();
        for (int i = tid; i < (TY + 2) * WPR; i += NT) {
            const int ly = i / WPR, lw = i - ly * WPR;
            const int gy = oy - 1 + ly, gx0 = ox - 4 + 4 * lw;
            unsigned int a = 0, c = 0;
            if ((unsigned)gy < HH && (unsigned)gx0 <= (WW - 4)) {
                const size_t o = base + (size_t)gy * WW + gx0;
                a = *(const unsigned int*)(g_bin[0] + o);
                c = *(const unsigned int*)(g_bin[1] + o);
            }
            rp[ly][lw] = a;
            rt[ly][lw] = c;
        }
        __syncthreads();
        // horizontal 1-2-1 per row (interior words 1..32)
        for (int i = tid; i < (TY + 2) * TX; i += NT) {
            const int row = i / TX, w = i - row * TX + 1;
            unsigned int l, c, rr;
            l = rp[row][w - 1]; c = rp[row][w]; rr = rp[row][w + 1];
            hp[row][w] = __byte_perm(c, l, 0x2107) + 2u * c + __byte_perm(c, rr, 0x4321);
            l = rt[row][w - 1]; c = rt[row][w]; rr = rt[row][w + 1];
            ht[row][w] = __byte_perm(c, l, 0x2107) + 2u * c + __byte_perm(c, rr, 0x4321);
        }
        // vertical 1-2-1 (all words)
        for (int i = tid; i < TY * WPR; i += NT) {
            const int vy = i / WPR, vw = i - vy * WPR;
            vp[vy][vw] = rp[vy][vw] + 2u * rp[vy + 1][vw] + rp[vy + 2][vw];
            vt[vy][vw] = rt[vy][vw] + 2u * rt[vy + 1][vw] + rt[vy + 2][vw];
        }
        __syncthreads();

        const int w = threadIdx.x + 1, ty = threadIdx.y;
        unsigned int vl, vc, vr;
        vl = vp[ty][w - 1]; vc = vp[ty][w]; vr = vp[ty][w + 1];
        const unsigned int pL = __byte_perm(vc, vl, 0x2107);
        const unsigned int pR = __byte_perm(vc, vr, 0x4321);
        const unsigned int ph0 = hp[ty][w], ph2 = hp[ty + 2][w];
        vl = vt[ty][w - 1]; vc = vt[ty][w]; vr = vt[ty][w + 1];
        const unsigned int tL = __byte_perm(vc, vl, 0x2107);
        const unsigned int tR = __byte_perm(vc, vr, 0x4321);
        const unsigned int th0 = ht[ty][w], th2 = ht[ty + 2][w];

        const size_t o = base + (size_t)(oy + ty) * WW + (ox + 4 * threadIdx.x);
        const unsigned int wp = *(const unsigned int*)(skp + o);
        const unsigned int wt = *(const unsigned int*)(skt + o);

#pragma unroll
        for (int k = 0; k < 4; k++) {
            const int sh = 8 * k;
            const int gxp = (int)((pR >> sh) & 0xFF) - (int)((pL >> sh) & 0xFF);
            const int gyp = (int)((ph2 >> sh) & 0xFF) - (int)((ph0 >> sh) & 0xFF);
            const float ep = lut[gxp * gxp + gyp * gyp];
            const int gxt = (int)((tR >> sh) & 0xFF) - (int)((tL >> sh) & 0xFF);
            const int gyt = (int)((th2 >> sh) & 0xFF) - (int)((th0 >> sh) & 0xFF);
            const float et = lut[gxt * gxt + gyt * gyt];
            const float ps = fminf((float)((wp >> sh) & 0xFF) + 0.5f * ep, 1.f);
            const float ts = fminf((float)((wt >> sh) & 0xFF) + 0.5f * et, 1.f);
            a5 += ps * ts;
            a6 += ps;
            a7 += ts;
        }
    }

    float r;
    r = block_reduce(a5, wb); if (tid == 0) atomicAdd(&g_acc[5], (double)r);
    r = block_reduce(a6, wb); if (tid == 0) atomicAdd(&g_acc[6], (double)r);
    r = block_reduce(a7, wb); if (tid == 0) atomicAdd(&g_acc[7], (double)r);

    if (tid == 0) {
        __threadfence();
        const unsigned int nb = gridDim.x * gridDim.y;
        const unsigned int tkt = atomicAdd(&g_cnt_sf, 1u);
        slast = (tkt == nb - 1);
    }
    __syncthreads();
    if (!slast) return;

    // ---- last block: combine + reset (all other blocks fully done by now) ----
    double v[8];
    if (tid == 0) {
#pragma unroll
        for (int i = 0; i < 8; i++) v[i] = atomicAdd(&g_acc[i], 0.0);
    }
    __syncthreads();
    if (tid < 8)  g_acc[tid] = 0.0;
    if (tid < NITER * 2) {
        ((unsigned long long*)g_itersum)[tid] = 0ull;
        ((unsigned int*)g_count)[tid] = 0u;
    }
    if (tid < 2) { g_done[tid] = 0; g_prev[tid] = -1LL; g_parity[tid] = 0; }
    if (tid == 31) g_cnt_sf = 0u;

    if (tid == 0) {
        const double di  = v[0], sp_ = v[1], st_ = v[2];
        const double fo  = v[3], co = v[4];
        const double ski = v[5], skps = v[6], skts = v[7];
        const double ntot = (double)B * HH * WW;

        const double skeleton = 1.0 - (2.0 * ski + 1.0) / (skps + skts + 1.0);
        const double dice     = 1.0 - (2.0 * di  + 1.0) / (sp_ + st_ + 1.0);
        double focal = fo / ntot;
        focal = fmin(fmax(focal, 0.0), 10.0);
        const double nw = st_;   // target is binary -> sum == water count
        const double conn = (nw == 0.0) ? 0.0 : co / fmax(nw, 1.0);

        double total = 0.3 * skeleton + 0.4 * dice + 0.2 * focal + 0.1 * conn;
        if (isnan(total) || isinf(total)) total = dice;
        out[0] = (float)total;
    }
}

// ---------------------------------------------------------------------------
extern "C" void kernel_launch(void* const* d_in, const int* in_sizes, int n_in,
                              void* d_out, int out_size) {
    const float* pred = (const float*)d_in[0];
    const float* tgt  = (const float*)d_in[1];
    const int N = in_sizes[0];
    const int B = N / (HH * WW);

    dim3 blk(TX, TY);
    dim3 grd(WW / EW, HH / TY, 1);      // 8 x 64
    dim3 grd2(WW / EW, HH / TY, 2);     // 8 x 64 x 2

    k_main<<<grd, blk>>>(pred, tgt, B);
    for (int f = 0; f < NF; ++f)
        k_erode2<<<grd2, blk>>>(f, B);
    k_skelfinal<<<grd, blk>>>(B, (float*)d_out);
}